// round 7
// baseline (speedup 1.0000x reference)
#include <cuda_runtime.h>
#include <cuda_fp16.h>
#include <math.h>

#define NN 100000
#define EE 1600000
#define EP (EE + NN)
#define HH 4
#define CC 32
#define DD 128
#define GG 64
#define LL 4
#define IN_DIM 7
#define NEG_SLOPE 0.2f

// ---------------- scratch ----------------
__device__ float  g_h[NN * DD];     // residual stream (fp32)
__device__ __half g_hp[NN * DD];    // projected features (fp16)
__device__ float  g_asrc[NN * HH];
__device__ float  g_adst[NN * HH];
__device__ int    g_cnt[NN];
__device__ int    g_off[NN + 1];
__device__ int    g_cur[NN];
__device__ int    g_csr[EP];
__device__ float  g_gsum[GG * DD];
__device__ float  g_gcnt[GG];

__device__ __forceinline__ float lrelu(float x) { return x > 0.0f ? x : NEG_SLOPE * x; }
__device__ __forceinline__ float elu(float x)   { return x > 0.0f ? x : expm1f(x); }
__device__ __forceinline__ unsigned f2tf32(float f) {
    unsigned u;
    asm("cvt.rna.tf32.f32 %0, %1;" : "=r"(u) : "f"(f));
    return u;
}

// ================= CSR build (once) =================
__global__ void csr_zero_kernel() {
    int i = blockIdx.x * blockDim.x + threadIdx.x;
    int stride = gridDim.x * blockDim.x;
    for (; i < NN; i += stride) g_cnt[i] = 0;
}

__global__ void csr_hist_kernel(const int* __restrict__ dst) {
    int e = blockIdx.x * blockDim.x + threadIdx.x;
    if (e < EP) {
        int d = (e < EE) ? dst[e] : (e - EE);
        atomicAdd(&g_cnt[d], 1);
    }
}

__global__ void csr_scan_kernel() {
    __shared__ int sh[1024];
    const int chunk = (NN + 1023) / 1024;
    int t = threadIdx.x;
    int b = t * chunk;
    int e = b + chunk; if (e > NN) e = NN;
    int s = 0;
    for (int i = b; i < e; i++) s += g_cnt[i];
    sh[t] = s;
    __syncthreads();
    for (int o = 1; o < 1024; o <<= 1) {
        int v = (t >= o) ? sh[t - o] : 0;
        __syncthreads();
        sh[t] += v;
        __syncthreads();
    }
    int run = (t == 0) ? 0 : sh[t - 1];
    for (int i = b; i < e; i++) {
        g_off[i] = run;
        g_cur[i] = run;
        run += g_cnt[i];
    }
    if (t == 1023) g_off[NN] = run;
}

__global__ void csr_scatter_kernel(const int* __restrict__ src, const int* __restrict__ dst) {
    int e = blockIdx.x * blockDim.x + threadIdx.x;
    if (e < EP) {
        int s, d;
        if (e < EE) { s = src[e]; d = dst[e]; } else { s = d = e - EE; }
        int pos = atomicAdd(&g_cur[d], 1);
        g_csr[pos] = s;
    }
}

// ================= layer-0 GEMM + alpha (warp per node) =================
__global__ __launch_bounds__(256) void gemm0_kernel(
    const float* __restrict__ x, const float* __restrict__ W0,
    const float* __restrict__ a_src, const float* __restrict__ a_dst)
{
    __shared__ float4 s_W[IN_DIM * 32];
    __shared__ float4 s_as[32], s_ad[32];
    if (threadIdx.x < IN_DIM * 32) s_W[threadIdx.x] = ((const float4*)W0)[threadIdx.x];
    if (threadIdx.x < 32) {
        s_as[threadIdx.x] = ((const float4*)a_src)[threadIdx.x];
        s_ad[threadIdx.x] = ((const float4*)a_dst)[threadIdx.x];
    }
    __syncthreads();
    int lane = threadIdx.x & 31;
    int wid = (blockIdx.x * blockDim.x + threadIdx.x) >> 5;
    int tw = (gridDim.x * blockDim.x) >> 5;
    for (int n = wid; n < NN; n += tw) {
        float xr[IN_DIM];
        #pragma unroll
        for (int k = 0; k < IN_DIM; k++) xr[k] = __ldg(&x[n * IN_DIM + k]);
        float4 acc = {0, 0, 0, 0};
        #pragma unroll
        for (int k = 0; k < IN_DIM; k++) {
            float4 wv = s_W[k * 32 + lane];
            acc.x += xr[k] * wv.x;
            acc.y += xr[k] * wv.y;
            acc.z += xr[k] * wv.z;
            acc.w += xr[k] * wv.w;
        }
        ((__half2*)g_hp)[(size_t)n * 64 + lane * 2]     = __floats2half2_rn(acc.x, acc.y);
        ((__half2*)g_hp)[(size_t)n * 64 + lane * 2 + 1] = __floats2half2_rn(acc.z, acc.w);
        float4 a = s_as[lane], b = s_ad[lane];
        float ps = acc.x * a.x + acc.y * a.y + acc.z * a.z + acc.w * a.w;
        float pd = acc.x * b.x + acc.y * b.y + acc.z * b.z + acc.w * b.w;
        #pragma unroll
        for (int o = 4; o > 0; o >>= 1) {
            ps += __shfl_down_sync(0xFFFFFFFFu, ps, o, 8);
            pd += __shfl_down_sync(0xFFFFFFFFu, pd, o, 8);
        }
        if ((lane & 7) == 0) {
            int h = lane >> 3;
            g_asrc[n * HH + h] = ps;
            g_adst[n * HH + h] = pd;
        }
    }
}

// ================= hidden GEMM (split-TF32 mma) + alpha epilogue ==========
// block = 256 thr (8 warps). M tile = 128 nodes; warp w -> rows [w*16, w*16+16).
// K chunked by 16. A = Ah + Al, B = Bh + Bl; C ≈ AhBh + AlBh + AhBl (fp32-accurate).
#define HS_STRIDE 20
#define WS_STRIDE 136
__global__ __launch_bounds__(256) void gemmH_mma_kernel(
    const float* __restrict__ Wg,
    const float* __restrict__ a_src, const float* __restrict__ a_dst)
{
    __shared__ unsigned HsH[128 * HS_STRIDE];
    __shared__ unsigned HsL[128 * HS_STRIDE];
    __shared__ unsigned WsH[16 * WS_STRIDE];
    __shared__ unsigned WsL[16 * WS_STRIDE];
    __shared__ float sA[DD], sB[DD];

    int t = threadIdx.x;
    int lane = t & 31;
    int w = t >> 5;
    int gid = lane >> 2;
    int tg = lane & 3;
    int n0 = blockIdx.x * 128;
    int m0 = w * 16;

    if (t < DD) { sA[t] = a_src[t]; sB[t] = a_dst[t]; }

    float acc[16][4];
    #pragma unroll
    for (int nt = 0; nt < 16; nt++)
        #pragma unroll
        for (int q = 0; q < 4; q++) acc[nt][q] = 0.0f;

    for (int kt = 0; kt < 8; kt++) {
        #pragma unroll
        for (int it = 0; it < 2; it++) {
            int idx = t + it * 256;
            int r = idx >> 2, q = idx & 3;
            float4 v = {0, 0, 0, 0};
            if (n0 + r < NN) v = ((const float4*)g_h)[(size_t)(n0 + r) * 32 + kt * 4 + q];
            unsigned* ph = &HsH[r * HS_STRIDE + q * 4];
            unsigned* pl = &HsL[r * HS_STRIDE + q * 4];
            float f[4] = {v.x, v.y, v.z, v.w};
            #pragma unroll
            for (int c = 0; c < 4; c++) {
                unsigned uh = f2tf32(f[c]);
                ph[c] = uh;
                pl[c] = f2tf32(f[c] - __uint_as_float(uh));
            }
        }
        #pragma unroll
        for (int it = 0; it < 2; it++) {
            int idx = t + it * 256;
            int r = idx >> 5, q = idx & 31;
            float4 v = ((const float4*)Wg)[(kt * 16 + r) * 32 + q];
            unsigned* ph = &WsH[r * WS_STRIDE + q * 4];
            unsigned* pl = &WsL[r * WS_STRIDE + q * 4];
            float f[4] = {v.x, v.y, v.z, v.w};
            #pragma unroll
            for (int c = 0; c < 4; c++) {
                unsigned uh = f2tf32(f[c]);
                ph[c] = uh;
                pl[c] = f2tf32(f[c] - __uint_as_float(uh));
            }
        }
        __syncthreads();

        #pragma unroll
        for (int kk = 0; kk < 2; kk++) {
            int r0 = (m0 + gid) * HS_STRIDE + kk * 8 + tg;
            int r1 = (m0 + gid + 8) * HS_STRIDE + kk * 8 + tg;
            unsigned ah0 = HsH[r0], ah1 = HsH[r1], ah2 = HsH[r0 + 4], ah3 = HsH[r1 + 4];
            unsigned al0 = HsL[r0], al1 = HsL[r1], al2 = HsL[r0 + 4], al3 = HsL[r1 + 4];
            #pragma unroll
            for (int nt = 0; nt < 16; nt++) {
                int c0 = (kk * 8 + tg) * WS_STRIDE + nt * 8 + gid;
                int c1 = (kk * 8 + tg + 4) * WS_STRIDE + nt * 8 + gid;
                unsigned bh0 = WsH[c0], bh1 = WsH[c1];
                unsigned bl0 = WsL[c0], bl1 = WsL[c1];
                asm volatile(
                    "mma.sync.aligned.m16n8k8.row.col.f32.tf32.tf32.f32 "
                    "{%0,%1,%2,%3}, {%4,%5,%6,%7}, {%8,%9}, {%0,%1,%2,%3};"
                    : "+f"(acc[nt][0]), "+f"(acc[nt][1]), "+f"(acc[nt][2]), "+f"(acc[nt][3])
                    : "r"(al0), "r"(al1), "r"(al2), "r"(al3), "r"(bh0), "r"(bh1));
                asm volatile(
                    "mma.sync.aligned.m16n8k8.row.col.f32.tf32.tf32.f32 "
                    "{%0,%1,%2,%3}, {%4,%5,%6,%7}, {%8,%9}, {%0,%1,%2,%3};"
                    : "+f"(acc[nt][0]), "+f"(acc[nt][1]), "+f"(acc[nt][2]), "+f"(acc[nt][3])
                    : "r"(ah0), "r"(ah1), "r"(ah2), "r"(ah3), "r"(bl0), "r"(bl1));
                asm volatile(
                    "mma.sync.aligned.m16n8k8.row.col.f32.tf32.tf32.f32 "
                    "{%0,%1,%2,%3}, {%4,%5,%6,%7}, {%8,%9}, {%0,%1,%2,%3};"
                    : "+f"(acc[nt][0]), "+f"(acc[nt][1]), "+f"(acc[nt][2]), "+f"(acc[nt][3])
                    : "r"(ah0), "r"(ah1), "r"(ah2), "r"(ah3), "r"(bh0), "r"(bh1));
            }
        }
        __syncthreads();
    }

    int na = n0 + m0 + gid;
    int nb = na + 8;
    #pragma unroll
    for (int nt = 0; nt < 16; nt++) {
        if (na < NN) ((__half2*)g_hp)[(size_t)na * 64 + nt * 4 + tg] = __floats2half2_rn(acc[nt][0], acc[nt][1]);
        if (nb < NN) ((__half2*)g_hp)[(size_t)nb * 64 + nt * 4 + tg] = __floats2half2_rn(acc[nt][2], acc[nt][3]);
    }
    float psa[4] = {0, 0, 0, 0}, pda[4] = {0, 0, 0, 0};
    float psb[4] = {0, 0, 0, 0}, pdb[4] = {0, 0, 0, 0};
    #pragma unroll
    for (int nt = 0; nt < 16; nt++) {
        int h = nt >> 2;
        int ch = nt * 8 + 2 * tg;
        float s0 = sA[ch], s1 = sA[ch + 1];
        float d0 = sB[ch], d1 = sB[ch + 1];
        psa[h] += acc[nt][0] * s0 + acc[nt][1] * s1;
        pda[h] += acc[nt][0] * d0 + acc[nt][1] * d1;
        psb[h] += acc[nt][2] * s0 + acc[nt][3] * s1;
        pdb[h] += acc[nt][2] * d0 + acc[nt][3] * d1;
    }
    #pragma unroll
    for (int h = 0; h < 4; h++) {
        #pragma unroll
        for (int o = 1; o < 4; o <<= 1) {
            psa[h] += __shfl_xor_sync(0xFFFFFFFFu, psa[h], o);
            pda[h] += __shfl_xor_sync(0xFFFFFFFFu, pda[h], o);
            psb[h] += __shfl_xor_sync(0xFFFFFFFFu, psb[h], o);
            pdb[h] += __shfl_xor_sync(0xFFFFFFFFu, pdb[h], o);
        }
    }
    if (tg == 0) {
        if (na < NN) {
            float4 v = {psa[0], psa[1], psa[2], psa[3]};
            ((float4*)g_asrc)[na] = v;
            float4 u = {pda[0], pda[1], pda[2], pda[3]};
            ((float4*)g_adst)[na] = u;
        }
        if (nb < NN) {
            float4 v = {psb[0], psb[1], psb[2], psb[3]};
            ((float4*)g_asrc)[nb] = v;
            float4 u = {pdb[0], pdb[1], pdb[2], pdb[3]};
            ((float4*)g_adst)[nb] = u;
        }
    }
}

// ================= fused one-pass edge aggregation + LN + ELU + residual ====
// warp per dst node; lane owns channels [lane*4, lane*4+4); head = lane>>3.
// No segment-max (softmax shift-invariance); logit clamped for safety.
__global__ __launch_bounds__(256) void fused_edge_kernel(
    const float* __restrict__ bias,
    const float* __restrict__ lng, const float* __restrict__ lnb,
    int is_first, int is_last, float* __restrict__ outp)
{
    int lane = threadIdx.x & 31;
    int h = lane >> 3;
    int wid = (blockIdx.x * blockDim.x + threadIdx.x) >> 5;
    int tw = (gridDim.x * blockDim.x) >> 5;
    int grp = lane & 24;
    int j8 = lane & 7;
    const uint2* hp2 = (const uint2*)g_hp;

    for (int d = wid; d < NN; d += tw) {
        int beg = g_off[d], end = g_off[d + 1];
        float4 ad4 = ((const float4*)g_adst)[d];
        float adh = (h == 0) ? ad4.x : (h == 1) ? ad4.y : (h == 2) ? ad4.z : ad4.w;

        float z = 0.0f;
        float4 acc = {0, 0, 0, 0};
        for (int c = beg; c < end; c += 8) {
            int i = c + j8;
            int s_own = 0;
            float e_own = 0.0f;
            if (i < end) {
                s_own = g_csr[i];
                float as = g_asrc[s_own * HH + h];
                e_own = __expf(fminf(lrelu(as + adh), 60.0f));
            }
            z += e_own;
            #pragma unroll
            for (int j = 0; j < 8; j++) {
                int sj   = __shfl_sync(0xFFFFFFFFu, s_own, grp | j);
                float ej = __shfl_sync(0xFFFFFFFFu, e_own, grp | j);
                uint2 hv = __ldg(&hp2[(size_t)sj * 32 + lane]);
                float2 f01 = __half22float2(*reinterpret_cast<const __half2*>(&hv.x));
                float2 f23 = __half22float2(*reinterpret_cast<const __half2*>(&hv.y));
                acc.x += ej * f01.x;
                acc.y += ej * f01.y;
                acc.z += ej * f23.x;
                acc.w += ej * f23.y;
            }
        }
        #pragma unroll
        for (int o = 4; o > 0; o >>= 1) z += __shfl_xor_sync(0xFFFFFFFFu, z, o, 8);
        float inv = 1.0f / (z + 1e-16f);

        float4 b4 = ((const float4*)bias)[lane];
        float4 v;
        v.x = acc.x * inv + b4.x;
        v.y = acc.y * inv + b4.y;
        v.z = acc.z * inv + b4.z;
        v.w = acc.w * inv + b4.w;

        float s  = v.x + v.y + v.z + v.w;
        float sq = v.x * v.x + v.y * v.y + v.z * v.z + v.w * v.w;
        #pragma unroll
        for (int o = 16; o > 0; o >>= 1) {
            s  += __shfl_xor_sync(0xFFFFFFFFu, s, o);
            sq += __shfl_xor_sync(0xFFFFFFFFu, sq, o);
        }
        float mu = s * (1.0f / 128.0f);
        float var = sq * (1.0f / 128.0f) - mu * mu;
        float rs = rsqrtf(var + 1e-5f);
        float4 gv = ((const float4*)lng)[lane];
        float4 bv = ((const float4*)lnb)[lane];
        float4 r;
        r.x = elu((v.x - mu) * rs * gv.x + bv.x);
        r.y = elu((v.y - mu) * rs * gv.y + bv.y);
        r.z = elu((v.z - mu) * rs * gv.z + bv.z);
        r.w = elu((v.w - mu) * rs * gv.w + bv.w);
        if (!is_first) {
            float4 hold = ((const float4*)g_h)[(size_t)d * 32 + lane];
            r.x += hold.x; r.y += hold.y; r.z += hold.z; r.w += hold.w;
        }
        ((float4*)g_h)[(size_t)d * 32 + lane] = r;
        if (is_last) ((float4*)outp)[(size_t)d * 32 + lane] = r;
    }
}

// ================= graph pooling =================
__global__ void pool_zero_kernel() {
    int tid = blockIdx.x * blockDim.x + threadIdx.x;
    int stride = gridDim.x * blockDim.x;
    for (int i = tid; i < GG * DD; i += stride) g_gsum[i] = 0.0f;
    for (int i = tid; i < GG; i += stride) g_gcnt[i] = 0.0f;
}

__global__ void pool_cnt_kernel(const int* __restrict__ batch) {
    __shared__ float c[GG];
    if (threadIdx.x < GG) c[threadIdx.x] = 0.0f;
    __syncthreads();
    int tid = blockIdx.x * blockDim.x + threadIdx.x;
    int stride = gridDim.x * blockDim.x;
    for (int n = tid; n < NN; n += stride) atomicAdd(&c[batch[n]], 1.0f);
    __syncthreads();
    if (threadIdx.x < GG && c[threadIdx.x] != 0.0f)
        atomicAdd(&g_gcnt[threadIdx.x], c[threadIdx.x]);
}

#define NPB 128
__global__ void pool_acc_kernel(const int* __restrict__ batch) {
    int j = threadIdx.x;
    int n0 = blockIdx.x * NPB;
    int n1 = n0 + NPB; if (n1 > NN) n1 = NN;
    if (n0 >= NN) return;
    int gcur = batch[n0];
    float acc = 0.0f;
    for (int n = n0; n < n1; n++) {
        int g = batch[n];
        if (g != gcur) {
            atomicAdd(&g_gsum[gcur * DD + j], acc);
            acc = 0.0f;
            gcur = g;
        }
        acc += g_h[(size_t)n * DD + j];
    }
    atomicAdd(&g_gsum[gcur * DD + j], acc);
}

__global__ void pool_fin_kernel(float* __restrict__ outp) {
    int i = blockIdx.x * blockDim.x + threadIdx.x;
    if (i < GG * DD) {
        int g = i >> 7;
        outp[NN * DD + i] = g_gsum[i] / fmaxf(g_gcnt[g], 1.0f);
    }
}

// ================= launch =================
extern "C" void kernel_launch(void* const* d_in, const int* in_sizes, int n_in,
                              void* d_out, int out_size) {
    const float* x      = (const float*)d_in[0];
    const int*   ei     = (const int*)  d_in[1];
    const int*   batch  = (const int*)  d_in[2];
    const float* W0     = (const float*)d_in[3];
    const float* a_src0 = (const float*)d_in[4];
    const float* a_dst0 = (const float*)d_in[5];
    const float* b0     = (const float*)d_in[6];
    const float* Ws     = (const float*)d_in[7];
    const float* a_srcs = (const float*)d_in[8];
    const float* a_dsts = (const float*)d_in[9];
    const float* bs     = (const float*)d_in[10];
    const float* ln_g   = (const float*)d_in[11];
    const float* ln_b   = (const float*)d_in[12];
    float* out = (float*)d_out;

    const int* srcp = ei;
    const int* dstp = ei + EE;

    csr_zero_kernel<<<256, 256>>>();
    csr_hist_kernel<<<(EP + 255) / 256, 256>>>(dstp);
    csr_scan_kernel<<<1, 1024>>>();
    csr_scatter_kernel<<<(EP + 255) / 256, 256>>>(srcp, dstp);

    for (int l = 0; l < LL; l++) {
        const float* asr  = (l == 0) ? a_src0 : (a_srcs + (l - 1) * HH * CC);
        const float* ads  = (l == 0) ? a_dst0 : (a_dsts + (l - 1) * HH * CC);
        const float* bias = (l == 0) ? b0     : (bs + (l - 1) * DD);

        if (l == 0)
            gemm0_kernel<<<1024, 256>>>(x, W0, asr, ads);
        else
            gemmH_mma_kernel<<<(NN + 127) / 128, 256>>>(Ws + (l - 1) * DD * DD, asr, ads);

        fused_edge_kernel<<<2048, 256>>>(bias, ln_g + l * DD, ln_b + l * DD,
                                         (l == 0) ? 1 : 0, (l == LL - 1) ? 1 : 0, out);
    }

    pool_zero_kernel<<<16, 256>>>();
    pool_cnt_kernel<<<256, 256>>>(batch);
    pool_acc_kernel<<<(NN + NPB - 1) / NPB, 128>>>(batch);
    pool_fin_kernel<<<(GG * DD + 255) / 256, 256>>>(out);
}

// round 8
// speedup vs baseline: 1.1822x; 1.1822x over previous
#include <cuda_runtime.h>
#include <cuda_fp16.h>
#include <math.h>

#define NN 100000
#define EE 1600000
#define EP (EE + NN)
#define HH 4
#define CC 32
#define DD 128
#define GG 64
#define LL 4
#define IN_DIM 7
#define NEG_SLOPE 0.2f

// ---------------- scratch ----------------
__device__ float  g_h[NN * DD];     // residual stream (fp32)
__device__ __half g_hp[NN * DD];    // projected features (fp16)
__device__ float  g_asrc[NN * HH];
__device__ float  g_adst[NN * HH];
__device__ int    g_cnt[NN];
__device__ int    g_off[NN + 1];
__device__ int    g_cur[NN];
__device__ int    g_csr[EP];
__device__ float  g_gsum[GG * DD];
__device__ float  g_gcnt[GG];

__device__ __forceinline__ float lrelu(float x) { return x > 0.0f ? x : NEG_SLOPE * x; }
__device__ __forceinline__ float elu(float x)   { return x > 0.0f ? x : expm1f(x); }
__device__ __forceinline__ unsigned f2tf32(float f) {
    unsigned u;
    asm("cvt.rna.tf32.f32 %0, %1;" : "=r"(u) : "f"(f));
    return u;
}

// ================= CSR build (once per call; dst layout layer-invariant) ====
__global__ void csr_zero_kernel() {
    int i = blockIdx.x * blockDim.x + threadIdx.x;
    int stride = gridDim.x * blockDim.x;
    for (; i < NN; i += stride) g_cnt[i] = 0;
}

__global__ void csr_hist_kernel(const int* __restrict__ dst) {
    int e = blockIdx.x * blockDim.x + threadIdx.x;
    if (e < EP) {
        int d = (e < EE) ? dst[e] : (e - EE);
        atomicAdd(&g_cnt[d], 1);
    }
}

__global__ void csr_scan_kernel() {
    __shared__ int sh[1024];
    const int chunk = (NN + 1023) / 1024;
    int t = threadIdx.x;
    int b = t * chunk;
    int e = b + chunk; if (e > NN) e = NN;
    int s = 0;
    for (int i = b; i < e; i++) s += g_cnt[i];
    sh[t] = s;
    __syncthreads();
    for (int o = 1; o < 1024; o <<= 1) {
        int v = (t >= o) ? sh[t - o] : 0;
        __syncthreads();
        sh[t] += v;
        __syncthreads();
    }
    int run = (t == 0) ? 0 : sh[t - 1];
    for (int i = b; i < e; i++) {
        g_off[i] = run;
        g_cur[i] = run;
        run += g_cnt[i];
    }
    if (t == 1023) g_off[NN] = run;
}

__global__ void csr_scatter_kernel(const int* __restrict__ src, const int* __restrict__ dst) {
    int e = blockIdx.x * blockDim.x + threadIdx.x;
    if (e < EP) {
        int s, d;
        if (e < EE) { s = src[e]; d = dst[e]; } else { s = d = e - EE; }
        int pos = atomicAdd(&g_cur[d], 1);
        g_csr[pos] = s;
    }
}

// ================= layer-0 GEMM + alpha (warp per node) =================
__global__ __launch_bounds__(256) void gemm0_kernel(
    const float* __restrict__ x, const float* __restrict__ W0,
    const float* __restrict__ a_src, const float* __restrict__ a_dst)
{
    __shared__ float4 s_W[IN_DIM * 32];
    __shared__ float4 s_as[32], s_ad[32];
    if (threadIdx.x < IN_DIM * 32) s_W[threadIdx.x] = ((const float4*)W0)[threadIdx.x];
    if (threadIdx.x < 32) {
        s_as[threadIdx.x] = ((const float4*)a_src)[threadIdx.x];
        s_ad[threadIdx.x] = ((const float4*)a_dst)[threadIdx.x];
    }
    __syncthreads();
    int lane = threadIdx.x & 31;
    int wid = (blockIdx.x * blockDim.x + threadIdx.x) >> 5;
    int tw = (gridDim.x * blockDim.x) >> 5;
    for (int n = wid; n < NN; n += tw) {
        float xr[IN_DIM];
        #pragma unroll
        for (int k = 0; k < IN_DIM; k++) xr[k] = __ldg(&x[n * IN_DIM + k]);
        float4 acc = {0, 0, 0, 0};
        #pragma unroll
        for (int k = 0; k < IN_DIM; k++) {
            float4 wv = s_W[k * 32 + lane];
            acc.x += xr[k] * wv.x;
            acc.y += xr[k] * wv.y;
            acc.z += xr[k] * wv.z;
            acc.w += xr[k] * wv.w;
        }
        ((__half2*)g_hp)[(size_t)n * 64 + lane * 2]     = __floats2half2_rn(acc.x, acc.y);
        ((__half2*)g_hp)[(size_t)n * 64 + lane * 2 + 1] = __floats2half2_rn(acc.z, acc.w);
        float4 a = s_as[lane], b = s_ad[lane];
        float ps = acc.x * a.x + acc.y * a.y + acc.z * a.z + acc.w * a.w;
        float pd = acc.x * b.x + acc.y * b.y + acc.z * b.z + acc.w * b.w;
        #pragma unroll
        for (int o = 4; o > 0; o >>= 1) {
            ps += __shfl_down_sync(0xFFFFFFFFu, ps, o, 8);
            pd += __shfl_down_sync(0xFFFFFFFFu, pd, o, 8);
        }
        if ((lane & 7) == 0) {
            int h = lane >> 3;
            g_asrc[n * HH + h] = ps;
            g_adst[n * HH + h] = pd;
        }
    }
}

// ================= hidden GEMM (single TF32 mma) + alpha epilogue ==========
// block = 256 thr (8 warps). M tile = 128 nodes; warp w -> rows [w*16, w*16+16).
#define HS_STRIDE 20
#define WS_STRIDE 136
__global__ __launch_bounds__(256) void gemmH_mma_kernel(
    const float* __restrict__ Wg,
    const float* __restrict__ a_src, const float* __restrict__ a_dst)
{
    __shared__ unsigned Hs[128 * HS_STRIDE];
    __shared__ unsigned Wsm[16 * WS_STRIDE];
    __shared__ float sA[DD], sB[DD];

    int t = threadIdx.x;
    int lane = t & 31;
    int w = t >> 5;
    int gid = lane >> 2;
    int tg = lane & 3;
    int n0 = blockIdx.x * 128;
    int m0 = w * 16;

    if (t < DD) { sA[t] = a_src[t]; sB[t] = a_dst[t]; }

    float acc[16][4];
    #pragma unroll
    for (int nt = 0; nt < 16; nt++)
        #pragma unroll
        for (int q = 0; q < 4; q++) acc[nt][q] = 0.0f;

    for (int kt = 0; kt < 8; kt++) {
        #pragma unroll
        for (int it = 0; it < 2; it++) {
            int idx = t + it * 256;
            int r = idx >> 2, q = idx & 3;
            float4 v = {0, 0, 0, 0};
            if (n0 + r < NN) v = ((const float4*)g_h)[(size_t)(n0 + r) * 32 + kt * 4 + q];
            unsigned* p = &Hs[r * HS_STRIDE + q * 4];
            p[0] = f2tf32(v.x); p[1] = f2tf32(v.y); p[2] = f2tf32(v.z); p[3] = f2tf32(v.w);
        }
        #pragma unroll
        for (int it = 0; it < 2; it++) {
            int idx = t + it * 256;
            int r = idx >> 5, q = idx & 31;
            float4 v = ((const float4*)Wg)[(kt * 16 + r) * 32 + q];
            unsigned* p = &Wsm[r * WS_STRIDE + q * 4];
            p[0] = f2tf32(v.x); p[1] = f2tf32(v.y); p[2] = f2tf32(v.z); p[3] = f2tf32(v.w);
        }
        __syncthreads();

        #pragma unroll
        for (int kk = 0; kk < 2; kk++) {
            unsigned a0 = Hs[(m0 + gid) * HS_STRIDE + kk * 8 + tg];
            unsigned a1 = Hs[(m0 + gid + 8) * HS_STRIDE + kk * 8 + tg];
            unsigned a2 = Hs[(m0 + gid) * HS_STRIDE + kk * 8 + tg + 4];
            unsigned a3 = Hs[(m0 + gid + 8) * HS_STRIDE + kk * 8 + tg + 4];
            #pragma unroll
            for (int nt = 0; nt < 16; nt++) {
                unsigned b0 = Wsm[(kk * 8 + tg) * WS_STRIDE + nt * 8 + gid];
                unsigned b1 = Wsm[(kk * 8 + tg + 4) * WS_STRIDE + nt * 8 + gid];
                asm volatile(
                    "mma.sync.aligned.m16n8k8.row.col.f32.tf32.tf32.f32 "
                    "{%0,%1,%2,%3}, {%4,%5,%6,%7}, {%8,%9}, {%0,%1,%2,%3};"
                    : "+f"(acc[nt][0]), "+f"(acc[nt][1]), "+f"(acc[nt][2]), "+f"(acc[nt][3])
                    : "r"(a0), "r"(a1), "r"(a2), "r"(a3), "r"(b0), "r"(b1));
            }
        }
        __syncthreads();
    }

    int na = n0 + m0 + gid;
    int nb = na + 8;
    #pragma unroll
    for (int nt = 0; nt < 16; nt++) {
        if (na < NN) ((__half2*)g_hp)[(size_t)na * 64 + nt * 4 + tg] = __floats2half2_rn(acc[nt][0], acc[nt][1]);
        if (nb < NN) ((__half2*)g_hp)[(size_t)nb * 64 + nt * 4 + tg] = __floats2half2_rn(acc[nt][2], acc[nt][3]);
    }
    float psa[4] = {0, 0, 0, 0}, pda[4] = {0, 0, 0, 0};
    float psb[4] = {0, 0, 0, 0}, pdb[4] = {0, 0, 0, 0};
    #pragma unroll
    for (int nt = 0; nt < 16; nt++) {
        int h = nt >> 2;
        int ch = nt * 8 + 2 * tg;
        float s0 = sA[ch], s1 = sA[ch + 1];
        float d0 = sB[ch], d1 = sB[ch + 1];
        psa[h] += acc[nt][0] * s0 + acc[nt][1] * s1;
        pda[h] += acc[nt][0] * d0 + acc[nt][1] * d1;
        psb[h] += acc[nt][2] * s0 + acc[nt][3] * s1;
        pdb[h] += acc[nt][2] * d0 + acc[nt][3] * d1;
    }
    #pragma unroll
    for (int h = 0; h < 4; h++) {
        #pragma unroll
        for (int o = 1; o < 4; o <<= 1) {
            psa[h] += __shfl_xor_sync(0xFFFFFFFFu, psa[h], o);
            pda[h] += __shfl_xor_sync(0xFFFFFFFFu, pda[h], o);
            psb[h] += __shfl_xor_sync(0xFFFFFFFFu, psb[h], o);
            pdb[h] += __shfl_xor_sync(0xFFFFFFFFu, pdb[h], o);
        }
    }
    if (tg == 0) {
        if (na < NN) {
            float4 v = {psa[0], psa[1], psa[2], psa[3]};
            ((float4*)g_asrc)[na] = v;
            float4 u = {pda[0], pda[1], pda[2], pda[3]};
            ((float4*)g_adst)[na] = u;
        }
        if (nb < NN) {
            float4 v = {psb[0], psb[1], psb[2], psb[3]};
            ((float4*)g_asrc)[nb] = v;
            float4 u = {pdb[0], pdb[1], pdb[2], pdb[3]};
            ((float4*)g_adst)[nb] = u;
        }
    }
}

// ================= fused one-pass edge aggregation + LN + ELU + residual ====
// warp per dst node; lane owns channels [lane*4, lane*4+4); head = lane>>3.
__global__ __launch_bounds__(256) void fused_edge_kernel(
    const float* __restrict__ bias,
    const float* __restrict__ lng, const float* __restrict__ lnb,
    int is_first, int is_last, float* __restrict__ outp)
{
    int lane = threadIdx.x & 31;
    int h = lane >> 3;
    int wid = (blockIdx.x * blockDim.x + threadIdx.x) >> 5;
    int tw = (gridDim.x * blockDim.x) >> 5;
    int grp = lane & 24;
    int j8 = lane & 7;
    const uint2* hp2 = (const uint2*)g_hp;

    for (int d = wid; d < NN; d += tw) {
        int beg = g_off[d], end = g_off[d + 1];
        float4 ad4 = ((const float4*)g_adst)[d];
        float adh = (h == 0) ? ad4.x : (h == 1) ? ad4.y : (h == 2) ? ad4.z : ad4.w;

        float z = 0.0f;
        float4 acc = {0, 0, 0, 0};
        for (int c = beg; c < end; c += 8) {
            int i = c + j8;
            int s_own = 0;
            float e_own = 0.0f;
            if (i < end) {
                s_own = g_csr[i];
                float as = g_asrc[s_own * HH + h];
                e_own = __expf(fminf(lrelu(as + adh), 60.0f));
            }
            z += e_own;
            int lim = end - c; if (lim > 8) lim = 8;
            for (int j = 0; j < lim; j++) {
                int sj   = __shfl_sync(0xFFFFFFFFu, s_own, grp | j);
                float ej = __shfl_sync(0xFFFFFFFFu, e_own, grp | j);
                uint2 hv = __ldg(&hp2[(size_t)sj * 32 + lane]);
                float2 f01 = __half22float2(*reinterpret_cast<const __half2*>(&hv.x));
                float2 f23 = __half22float2(*reinterpret_cast<const __half2*>(&hv.y));
                acc.x += ej * f01.x;
                acc.y += ej * f01.y;
                acc.z += ej * f23.x;
                acc.w += ej * f23.y;
            }
        }
        #pragma unroll
        for (int o = 4; o > 0; o >>= 1) z += __shfl_xor_sync(0xFFFFFFFFu, z, o, 8);
        float inv = 1.0f / (z + 1e-16f);

        float4 b4 = ((const float4*)bias)[lane];
        float4 v;
        v.x = acc.x * inv + b4.x;
        v.y = acc.y * inv + b4.y;
        v.z = acc.z * inv + b4.z;
        v.w = acc.w * inv + b4.w;

        float s  = v.x + v.y + v.z + v.w;
        float sq = v.x * v.x + v.y * v.y + v.z * v.z + v.w * v.w;
        #pragma unroll
        for (int o = 16; o > 0; o >>= 1) {
            s  += __shfl_xor_sync(0xFFFFFFFFu, s, o);
            sq += __shfl_xor_sync(0xFFFFFFFFu, sq, o);
        }
        float mu = s * (1.0f / 128.0f);
        float var = sq * (1.0f / 128.0f) - mu * mu;
        float rs = rsqrtf(var + 1e-5f);
        float4 gv = ((const float4*)lng)[lane];
        float4 bv = ((const float4*)lnb)[lane];
        float4 r;
        r.x = elu((v.x - mu) * rs * gv.x + bv.x);
        r.y = elu((v.y - mu) * rs * gv.y + bv.y);
        r.z = elu((v.z - mu) * rs * gv.z + bv.z);
        r.w = elu((v.w - mu) * rs * gv.w + bv.w);
        if (!is_first) {
            float4 hold = ((const float4*)g_h)[(size_t)d * 32 + lane];
            r.x += hold.x; r.y += hold.y; r.z += hold.z; r.w += hold.w;
        }
        ((float4*)g_h)[(size_t)d * 32 + lane] = r;
        if (is_last) ((float4*)outp)[(size_t)d * 32 + lane] = r;
    }
}

// ================= graph pooling =================
__global__ void pool_zero_kernel() {
    int tid = blockIdx.x * blockDim.x + threadIdx.x;
    int stride = gridDim.x * blockDim.x;
    for (int i = tid; i < GG * DD; i += stride) g_gsum[i] = 0.0f;
    for (int i = tid; i < GG; i += stride) g_gcnt[i] = 0.0f;
}

__global__ void pool_cnt_kernel(const int* __restrict__ batch) {
    __shared__ float c[GG];
    if (threadIdx.x < GG) c[threadIdx.x] = 0.0f;
    __syncthreads();
    int tid = blockIdx.x * blockDim.x + threadIdx.x;
    int stride = gridDim.x * blockDim.x;
    for (int n = tid; n < NN; n += stride) atomicAdd(&c[batch[n]], 1.0f);
    __syncthreads();
    if (threadIdx.x < GG && c[threadIdx.x] != 0.0f)
        atomicAdd(&g_gcnt[threadIdx.x], c[threadIdx.x]);
}

#define NPB 128
__global__ void pool_acc_kernel(const int* __restrict__ batch) {
    int j = threadIdx.x;
    int n0 = blockIdx.x * NPB;
    int n1 = n0 + NPB; if (n1 > NN) n1 = NN;
    if (n0 >= NN) return;
    int gcur = batch[n0];
    float acc = 0.0f;
    for (int n = n0; n < n1; n++) {
        int g = batch[n];
        if (g != gcur) {
            atomicAdd(&g_gsum[gcur * DD + j], acc);
            acc = 0.0f;
            gcur = g;
        }
        acc += g_h[(size_t)n * DD + j];
    }
    atomicAdd(&g_gsum[gcur * DD + j], acc);
}

__global__ void pool_fin_kernel(float* __restrict__ outp) {
    int i = blockIdx.x * blockDim.x + threadIdx.x;
    if (i < GG * DD) {
        int g = i >> 7;
        outp[NN * DD + i] = g_gsum[i] / fmaxf(g_gcnt[g], 1.0f);
    }
}

// ================= launch =================
extern "C" void kernel_launch(void* const* d_in, const int* in_sizes, int n_in,
                              void* d_out, int out_size) {
    const float* x      = (const float*)d_in[0];
    const int*   ei     = (const int*)  d_in[1];
    const int*   batch  = (const int*)  d_in[2];
    const float* W0     = (const float*)d_in[3];
    const float* a_src0 = (const float*)d_in[4];
    const float* a_dst0 = (const float*)d_in[5];
    const float* b0     = (const float*)d_in[6];
    const float* Ws     = (const float*)d_in[7];
    const float* a_srcs = (const float*)d_in[8];
    const float* a_dsts = (const float*)d_in[9];
    const float* bs     = (const float*)d_in[10];
    const float* ln_g   = (const float*)d_in[11];
    const float* ln_b   = (const float*)d_in[12];
    float* out = (float*)d_out;

    const int* srcp = ei;
    const int* dstp = ei + EE;

    csr_zero_kernel<<<256, 256>>>();
    csr_hist_kernel<<<(EP + 255) / 256, 256>>>(dstp);
    csr_scan_kernel<<<1, 1024>>>();
    csr_scatter_kernel<<<(EP + 255) / 256, 256>>>(srcp, dstp);

    for (int l = 0; l < LL; l++) {
        const float* asr  = (l == 0) ? a_src0 : (a_srcs + (l - 1) * HH * CC);
        const float* ads  = (l == 0) ? a_dst0 : (a_dsts + (l - 1) * HH * CC);
        const float* bias = (l == 0) ? b0     : (bs + (l - 1) * DD);

        if (l == 0)
            gemm0_kernel<<<1024, 256>>>(x, W0, asr, ads);
        else
            gemmH_mma_kernel<<<(NN + 127) / 128, 256>>>(Ws + (l - 1) * DD * DD, asr, ads);

        fused_edge_kernel<<<2048, 256>>>(bias, ln_g + l * DD, ln_b + l * DD,
                                         (l == 0) ? 1 : 0, (l == LL - 1) ? 1 : 0, out);
    }

    pool_zero_kernel<<<16, 256>>>();
    pool_cnt_kernel<<<256, 256>>>(batch);
    pool_acc_kernel<<<(NN + NPB - 1) / NPB, 128>>>(batch);
    pool_fin_kernel<<<(GG * DD + 255) / 256, 256>>>(out);
}